// round 8
// baseline (speedup 1.0000x reference)
#include <cuda_runtime.h>
#include <stdint.h>

#define BB 16
#define PP 8192
#define MM 128
#define KNN 16
#define DD 768
#define QQ (BB*MM)      // 2048 queries/tokens
#define RR (QQ*KNN)     // 32768 gathered rows

// ---------------- scratch (device globals; no allocation allowed) ----------------
__device__ float g_cent[QQ*4];
__device__ int   g_knn[RR];
__device__ float g_bufA[(size_t)RR*768];
__device__ float g_bufB[(size_t)RR*768];
__device__ float g_pool[(size_t)QQ*DD];
__device__ float g_h[(size_t)QQ*DD];
// transposed weights [N][K] (K-major so B operand is n-major/k-contiguous = "col" for mma)
#define OFF_W2T  0
#define OFF_W3T  (512*256)
#define OFF_W4T  (OFF_W3T + 768*512)
#define OFF_WA1T (OFF_W4T + 768*768)
#define OFF_WA2T (OFF_WA1T + 768*768)
__device__ float g_wt[OFF_WA2T + 768*768];

__device__ __forceinline__ uint32_t f2tf32(float x) {
    uint32_t u; asm("cvt.rn.tf32.f32 %0, %1;" : "=r"(u) : "f"(x)); return u;
}
__device__ __forceinline__ float tf32r(float x) {
    return __uint_as_float(f2tf32(x));
}

// ---------------- FPS: one block per batch, points register-resident -------------
__global__ __launch_bounds__(1024) void fps_kernel(const float* __restrict__ coords,
                                                   float* __restrict__ cent_out2)
{
    int b = blockIdx.x;
    int tid = threadIdx.x;
    float px[8], py[8], pz[8], pw[8], dmin[8];
#pragma unroll
    for (int i = 0; i < 8; i++) {
        int p = tid + i * 1024;
        const float* c = coords + ((size_t)b * PP + p) * 5;
        px[i] = c[1]; py[i] = c[2]; pz[i] = c[3]; pw[i] = c[4];
        dmin[i] = 1e30f;
    }
    __shared__ float last[4];
    __shared__ unsigned long long red[32];
    __shared__ int cur_s;
    int cur = 0;
    for (int m = 0; m < MM; m++) {
        if (tid == (cur & 1023)) {
            int i = cur >> 10;
            last[0] = px[i]; last[1] = py[i]; last[2] = pz[i]; last[3] = pw[i];
            float* o  = g_cent + ((size_t)b * MM + m) * 4;
            o[0] = px[i]; o[1] = py[i]; o[2] = pz[i]; o[3] = pw[i];
            float* o2 = cent_out2 + ((size_t)b * MM + m) * 4;
            o2[0] = px[i]; o2[1] = py[i]; o2[2] = pz[i]; o2[3] = pw[i];
        }
        __syncthreads();
        if (m == MM - 1) break;
        float lx = last[0], ly = last[1], lz = last[2], lw = last[3];
        unsigned long long best = 0ull;
#pragma unroll
        for (int i = 0; i < 8; i++) {
            float dx = __fsub_rn(px[i], lx);
            float dy = __fsub_rn(py[i], ly);
            float dz = __fsub_rn(pz[i], lz);
            float dw = __fsub_rn(pw[i], lw);
            float d = __fadd_rn(__fadd_rn(__fadd_rn(__fmul_rn(dx,dx), __fmul_rn(dy,dy)),
                                          __fmul_rn(dz,dz)), __fmul_rn(dw,dw));
            float dm = fminf(dmin[i], d);
            dmin[i] = dm;
            unsigned long long key = ((unsigned long long)__float_as_uint(dm) << 32)
                                   | (unsigned)(0x7FFFFFFF - (tid + i * 1024));
            if (key > best) best = key;
        }
        for (int off = 16; off; off >>= 1) {
            unsigned long long o = __shfl_down_sync(0xFFFFFFFFu, best, off);
            if (o > best) best = o;
        }
        if ((tid & 31) == 0) red[tid >> 5] = best;
        __syncthreads();
        if (tid < 32) {
            unsigned long long v = red[tid];
            for (int off = 16; off; off >>= 1) {
                unsigned long long o = __shfl_down_sync(0xFFFFFFFFu, v, off);
                if (o > v) v = o;
            }
            if (tid == 0) cur_s = 0x7FFFFFFF - (int)(v & 0xFFFFFFFFu);
        }
        __syncthreads();
        cur = cur_s;
    }
}

// ---------------- kNN: register top-16 per thread + 256-way sorted merge ----------
// Distances computed with the EXACT same fp32 op sequence as before -> identical picks.
__global__ __launch_bounds__(256) void knn_kernel(const float* __restrict__ coords,
                                                  int* __restrict__ knn)
{
    __shared__ unsigned long long skeys[256 * 17];   // padded: conflict-free heads
    __shared__ unsigned long long red[8];
    __shared__ unsigned long long win_s;
    int m = blockIdx.x, b = blockIdx.y;
    int tid = threadIdx.x;
    const float* c = g_cent + ((size_t)b * MM + m) * 4;
    float c0 = c[0], c1 = c[1], c2 = c[2], c3 = c[3];
    float cen2 = __fadd_rn(__fadd_rn(__fadd_rn(__fmul_rn(c0,c0), __fmul_rn(c1,c1)),
                                     __fmul_rn(c2,c2)), __fmul_rn(c3,c3));

    // phase 1: per-thread sorted top-16 over 32 strided points
    unsigned long long lst[KNN];
#pragma unroll
    for (int i = 0; i < KNN; i++) lst[i] = ~0ull;

#pragma unroll 4
    for (int it = 0; it < PP / 256; it++) {
        int p = tid + it * 256;
        const float* q = coords + ((size_t)b * PP + p) * 5;
        float x0 = q[1], x1 = q[2], x2 = q[3], x3 = q[4];
        float pts2 = __fadd_rn(__fadd_rn(__fadd_rn(__fmul_rn(x0,x0), __fmul_rn(x1,x1)),
                                         __fmul_rn(x2,x2)), __fmul_rn(x3,x3));
        float dot  = __fadd_rn(__fadd_rn(__fadd_rn(__fmul_rn(c0,x0), __fmul_rn(c1,x1)),
                                         __fmul_rn(c2,x2)), __fmul_rn(c3,x3));
        float d2 = __fsub_rn(__fadd_rn(cen2, pts2), __fmul_rn(2.0f, dot));
        unsigned u = __float_as_uint(d2);
        u = (u & 0x80000000u) ? ~u : (u | 0x80000000u);   // order-preserving map
        unsigned long long key = ((unsigned long long)u << 32) | (unsigned)p;
        if (key < lst[KNN - 1]) {
            lst[KNN - 1] = key;
#pragma unroll
            for (int i = KNN - 1; i > 0; i--) {
                if (lst[i] < lst[i - 1]) {
                    unsigned long long t = lst[i]; lst[i] = lst[i - 1]; lst[i - 1] = t;
                } else break;
            }
        }
    }
    // dump sorted lists to smem
#pragma unroll
    for (int i = 0; i < KNN; i++) skeys[tid * 17 + i] = lst[i];
    __syncthreads();

    // phase 2: 16 rounds of 256-way merge (pop global min of per-thread heads)
    int head = 0;
    int* outp = knn + ((size_t)b * MM + m) * KNN;
    for (int k = 0; k < KNN; k++) {
        unsigned long long myprop = (head < KNN) ? skeys[tid * 17 + head] : ~0ull;
        unsigned long long v = myprop;
        for (int off = 16; off; off >>= 1) {
            unsigned long long o = __shfl_down_sync(0xFFFFFFFFu, v, off);
            if (o < v) v = o;
        }
        if ((tid & 31) == 0) red[tid >> 5] = v;
        __syncthreads();
        if (tid == 0) {
            unsigned long long w = red[0];
#pragma unroll
            for (int j = 1; j < 8; j++) if (red[j] < w) w = red[j];
            win_s = w;
            outp[k] = (int)(w & 0xFFFFFFFFu);
        }
        __syncthreads();
        if (myprop == win_s) head++;
    }
}

// ---------------- gather + layer1 (6 -> 256, relu): 8 rows per block --------------
__global__ __launch_bounds__(256) void gather_mlp1(const float* __restrict__ feats,
                                                   const float* __restrict__ W1,
                                                   const float* __restrict__ b1)
{
    int j = threadIdx.x;
    int rowbase = blockIdx.x * 8;
    float w[6];
#pragma unroll
    for (int t = 0; t < 6; t++) w[t] = W1[t * 256 + j];
    float bb = b1[j];
    __shared__ float fs[8][6];
    if (j < 48) {
        int r = j / 6, cidx = j % 6;
        int row = rowbase + r;
        int bidx = row >> 11;                       // row / (MM*KNN)
        int idx = g_knn[row];
        fs[r][cidx] = feats[((size_t)bidx * PP + idx) * 6 + cidx];
    }
    __syncthreads();
#pragma unroll
    for (int r = 0; r < 8; r++) {
        float acc = bb;
#pragma unroll
        for (int t = 0; t < 6; t++) acc = fmaf(fs[r][t], w[t], acc);
        g_bufA[(size_t)(rowbase + r) * 256 + j] = tf32r(fmaxf(acc, 0.f));
    }
}

// ---------------- all weight transposes in one kernel ------------------------------
// Wt[n][k] = round_tf32(W[k][n]) for the 5 weight matrices.
#define TN_W2  (256*512)
#define TN_W3  (512*768)
#define TN_W44 (768*768)
#define TE1 TN_W2
#define TE2 (TE1 + TN_W3)
#define TE3 (TE2 + TN_W44)
#define TE4 (TE3 + TN_W44)
#define TE5 (TE4 + TN_W44)
__global__ __launch_bounds__(256) void transpose_all(
    const float* __restrict__ W2, const float* __restrict__ W3,
    const float* __restrict__ W4, const float* __restrict__ Wa1,
    const float* __restrict__ Wa2, float* __restrict__ Wt)
{
    int i = blockIdx.x * 256 + threadIdx.x;
    const float* W; float* dst; int N, K, j;
    if (i < TE1)      { j = i;       W = W2;  dst = Wt + OFF_W2T;  K = 256; N = 512; }
    else if (i < TE2) { j = i - TE1; W = W3;  dst = Wt + OFF_W3T;  K = 512; N = 768; }
    else if (i < TE3) { j = i - TE2; W = W4;  dst = Wt + OFF_W4T;  K = 768; N = 768; }
    else if (i < TE4) { j = i - TE3; W = Wa1; dst = Wt + OFF_WA1T; K = 768; N = 768; }
    else if (i < TE5) { j = i - TE4; W = Wa2; dst = Wt + OFF_WA2T; K = 768; N = 768; }
    else return;
    int k = j / N, n = j % N;
    dst[(size_t)n * K + k] = tf32r(W[j]);
}

// ================= tf32 mma.sync GEMM, 3-stage cp.async pipeline ===================
// C[Mr,N] = act(A[Mr,K] @ Bt[N,K]^T + bias)    (A, Bt already tf32-rounded fp32)
// CTA tile 128x128. K staged in chunks of 32. 8 warps: 4(m) x 2(n), warp tile 32x64.
#define SPAD 36                      // smem row stride in words (conflict-free, 16B-OK)
#define STG_MAT (128 * SPAD * 4)     // 18432 B per matrix per stage
#define STG_BYTES (2 * STG_MAT)      // 36864 B per stage (A + B)
#define NSTAGE 3
#define GSMEM (NSTAGE * STG_BYTES)   // 110592 B

__device__ __forceinline__ void cp16(uint32_t saddr, const void* g) {
    asm volatile("cp.async.cg.shared.global [%0], [%1], 16;" :: "r"(saddr), "l"(g));
}

template<bool RELU, bool ROUND>
__global__ __launch_bounds__(256) void mma_gemm(
    const float* __restrict__ A, const float* __restrict__ Bt,
    const float* __restrict__ bias, float* __restrict__ C,
    int N, int K)
{
    extern __shared__ char dsm[];
    uint32_t sbase = (uint32_t)__cvta_generic_to_shared(dsm);
    int tid = threadIdx.x, wid = tid >> 5, lane = tid & 31;
    int gid = lane >> 2, tig = lane & 3;
    int bx = blockIdx.x, by = blockIdx.y;
    int m_base = (wid & 3) * 32;
    int n_base = (wid >> 2) * 64;

    const float* Ag = A  + (size_t)(by * 128) * K;
    const float* Bg = Bt + (size_t)(bx * 128) * K;

    int srow[4], sc4[4];
#pragma unroll
    for (int r = 0; r < 4; r++) {
        int id = tid + 256 * r;
        srow[r] = id >> 3;
        sc4[r]  = id & 7;
    }

    float acc[2][8][4];
#pragma unroll
    for (int mt = 0; mt < 2; mt++)
#pragma unroll
        for (int nt = 0; nt < 8; nt++)
#pragma unroll
            for (int j = 0; j < 4; j++) acc[mt][nt][j] = 0.f;

    int NC = K >> 5;

#pragma unroll
    for (int s = 0; s < 2; s++) {
        int kb = s << 5;
        uint32_t stb = sbase + s * STG_BYTES;
#pragma unroll
        for (int r = 0; r < 4; r++) {
            uint32_t doff = (uint32_t)(srow[r] * (SPAD * 4) + sc4[r] * 16);
            cp16(stb + doff,           Ag + (size_t)srow[r] * K + kb + sc4[r] * 4);
            cp16(stb + STG_MAT + doff, Bg + (size_t)srow[r] * K + kb + sc4[r] * 4);
        }
        asm volatile("cp.async.commit_group;" ::: "memory");
    }

    for (int c = 0; c < NC; c++) {
        asm volatile("cp.async.wait_group 1;" ::: "memory");
        __syncthreads();

        if (c + 2 < NC) {
            int kb = (c + 2) << 5;
            uint32_t stb = sbase + ((c + 2) % NSTAGE) * STG_BYTES;
#pragma unroll
            for (int r = 0; r < 4; r++) {
                uint32_t doff = (uint32_t)(srow[r] * (SPAD * 4) + sc4[r] * 16);
                cp16(stb + doff,           Ag + (size_t)srow[r] * K + kb + sc4[r] * 4);
                cp16(stb + STG_MAT + doff, Bg + (size_t)srow[r] * K + kb + sc4[r] * 4);
            }
        }
        asm volatile("cp.async.commit_group;" ::: "memory");

        const uint32_t* As = (const uint32_t*)(dsm + (c % NSTAGE) * STG_BYTES);
        const uint32_t* Bs = As + 128 * SPAD;

#pragma unroll
        for (int ks = 0; ks < 4; ks++) {
            int k0 = ks * 8;
            uint32_t af[2][4];
#pragma unroll
            for (int mt = 0; mt < 2; mt++) {
                int row = m_base + mt * 16 + gid;
                af[mt][0] = As[row * SPAD + k0 + tig];
                af[mt][1] = As[(row + 8) * SPAD + k0 + tig];
                af[mt][2] = As[row * SPAD + k0 + tig + 4];
                af[mt][3] = As[(row + 8) * SPAD + k0 + tig + 4];
            }
#pragma unroll
            for (int nt = 0; nt < 8; nt++) {
                int col = n_base + nt * 8 + gid;
                uint32_t b0 = Bs[col * SPAD + k0 + tig];
                uint32_t b1 = Bs[col * SPAD + k0 + tig + 4];
#pragma unroll
                for (int mt = 0; mt < 2; mt++) {
                    asm volatile(
                        "mma.sync.aligned.m16n8k8.row.col.f32.tf32.tf32.f32 "
                        "{%0,%1,%2,%3}, {%4,%5,%6,%7}, {%8,%9}, {%0,%1,%2,%3};"
                        : "+f"(acc[mt][nt][0]), "+f"(acc[mt][nt][1]),
                          "+f"(acc[mt][nt][2]), "+f"(acc[mt][nt][3])
                        : "r"(af[mt][0]), "r"(af[mt][1]), "r"(af[mt][2]), "r"(af[mt][3]),
                          "r"(b0), "r"(b1));
                }
            }
        }
    }

#pragma unroll
    for (int nt = 0; nt < 8; nt++) {
        int cg = bx * 128 + n_base + nt * 8 + 2 * tig;
        float bz0 = bias[cg], bz1 = bias[cg + 1];
#pragma unroll
        for (int mt = 0; mt < 2; mt++) {
            int rg = by * 128 + m_base + mt * 16 + gid;
            float v0 = acc[mt][nt][0] + bz0;
            float v1 = acc[mt][nt][1] + bz1;
            float v2 = acc[mt][nt][2] + bz0;
            float v3 = acc[mt][nt][3] + bz1;
            if (RELU) {
                v0 = fmaxf(v0, 0.f); v1 = fmaxf(v1, 0.f);
                v2 = fmaxf(v2, 0.f); v3 = fmaxf(v3, 0.f);
            }
            if (ROUND) {
                v0 = tf32r(v0); v1 = tf32r(v1);
                v2 = tf32r(v2); v3 = tf32r(v3);
            }
            *(float2*)(C + (size_t)rg * N + cg)       = make_float2(v0, v1);
            *(float2*)(C + (size_t)(rg + 8) * N + cg) = make_float2(v2, v3);
        }
    }
}

// ---------------- max-pool over K neighbors (inputs tf32-rounded; max preserves) ---
__global__ __launch_bounds__(256) void maxpool_kernel()
{
    int i = blockIdx.x * 256 + threadIdx.x;
    if (i >= QQ * DD) return;
    int q = i / DD, d = i % DD;
    const float* p = g_bufB + ((size_t)q * KNN) * DD + d;
    float v = p[0];
#pragma unroll
    for (int k = 1; k < KNN; k++) v = fmaxf(v, p[(size_t)k * DD]);
    g_pool[i] = v;
}

// ---------------- mask fill --------------------------------------------------------
__global__ void fill_mask(float* m)
{
    int i = blockIdx.x * 256 + threadIdx.x;
    if (i < QQ) m[i] = 1.0f;
}

// ---------------- launcher ---------------------------------------------------------
extern "C" void kernel_launch(void* const* d_in, const int* in_sizes, int n_in,
                              void* d_out, int out_size)
{
    const float* coords = (const float*)d_in[0];
    const float* feats  = (const float*)d_in[1];
    const float* W1 = (const float*)d_in[2];  const float* b1 = (const float*)d_in[3];
    const float* W2 = (const float*)d_in[4];  const float* b2 = (const float*)d_in[5];
    const float* W3 = (const float*)d_in[6];  const float* b3 = (const float*)d_in[7];
    const float* W4 = (const float*)d_in[8];  const float* b4 = (const float*)d_in[9];
    const float* Wa1 = (const float*)d_in[10]; const float* ba1 = (const float*)d_in[11];
    const float* Wa2 = (const float*)d_in[12]; const float* ba2 = (const float*)d_in[13];

    float* out     = (float*)d_out;
    float* tokens  = out;                               // [QQ, DD]
    float* centout = out + (size_t)QQ * DD;             // [QQ, 4]
    float* masks   = centout + (size_t)QQ * 4;          // [QQ]

    float *pA, *pB, *pPool, *pH, *pWt;
    int* pKnn;
    cudaGetSymbolAddress((void**)&pA, g_bufA);
    cudaGetSymbolAddress((void**)&pB, g_bufB);
    cudaGetSymbolAddress((void**)&pPool, g_pool);
    cudaGetSymbolAddress((void**)&pH, g_h);
    cudaGetSymbolAddress((void**)&pKnn, g_knn);
    cudaGetSymbolAddress((void**)&pWt, g_wt);

    // 1. FPS -> centroids
    fps_kernel<<<BB, 1024>>>(coords, centout);

    // 2. weight transposes (single kernel; independent of FPS output)
    transpose_all<<<(TE5 + 255) / 256, 256>>>(W2, W3, W4, Wa1, Wa2, pWt);

    // 3. kNN (register top-16 + merge; static smem only)
    knn_kernel<<<dim3(MM, BB), 256>>>(coords, pKnn);

    // 4. gather + layer1 (6 -> 256, relu, tf32-rounded) -> g_bufA
    gather_mlp1<<<RR / 8, 256>>>(feats, W1, b1);

    // 5. MLP chain on tensor cores (tf32 mma.sync, cp.async pipelined)
    cudaFuncSetAttribute((const void*)mma_gemm<true,  true >, cudaFuncAttributeMaxDynamicSharedMemorySize, GSMEM);
    cudaFuncSetAttribute((const void*)mma_gemm<false, true >, cudaFuncAttributeMaxDynamicSharedMemorySize, GSMEM);
    cudaFuncSetAttribute((const void*)mma_gemm<false, false>, cudaFuncAttributeMaxDynamicSharedMemorySize, GSMEM);
    mma_gemm<true,  true ><<<dim3(512 / 128, RR / 128), 256, GSMEM>>>(pA, pWt + OFF_W2T, b2, pB, 512, 256);
    mma_gemm<true,  true ><<<dim3(768 / 128, RR / 128), 256, GSMEM>>>(pB, pWt + OFF_W3T, b3, pA, 768, 512);
    mma_gemm<false, true ><<<dim3(768 / 128, RR / 128), 256, GSMEM>>>(pA, pWt + OFF_W4T, b4, pB, 768, 768);

    // 6. max-pool over K (keeps tf32-rounded values)
    maxpool_kernel<<<(QQ * DD + 255) / 256, 256>>>();

    // 7. attention MLP -> tokens
    mma_gemm<true,  true ><<<dim3(DD / 128, QQ / 128), 256, GSMEM>>>(pPool, pWt + OFF_WA1T, ba1, pH, 768, 768);
    mma_gemm<false, false><<<dim3(DD / 128, QQ / 128), 256, GSMEM>>>(pH, pWt + OFF_WA2T, ba2, tokens, 768, 768);

    // 8. masks
    fill_mask<<<(QQ + 255) / 256, 256>>>(masks);
}

// round 9
// speedup vs baseline: 1.2401x; 1.2401x over previous
#include <cuda_runtime.h>
#include <stdint.h>

#define BB 16
#define PP 8192
#define MM 128
#define KNN 16
#define DD 768
#define QQ (BB*MM)      // 2048 queries/tokens
#define RR (QQ*KNN)     // 32768 gathered rows

// ---------------- scratch (device globals; no allocation allowed) ----------------
__device__ float g_cent[QQ*4];
__device__ int   g_knn[RR];
__device__ float g_bufA[(size_t)RR*768];
__device__ float g_bufB[(size_t)RR*768];
__device__ float g_pool[(size_t)QQ*DD];
__device__ float g_h[(size_t)QQ*DD];
// transposed weights [N][K] (K-major so B operand is n-major/k-contiguous = "col" for mma)
#define OFF_W2T  0
#define OFF_W3T  (512*256)
#define OFF_W4T  (OFF_W3T + 768*512)
#define OFF_WA1T (OFF_W4T + 768*768)
#define OFF_WA2T (OFF_WA1T + 768*768)
__device__ float g_wt[OFF_WA2T + 768*768];

__device__ __forceinline__ uint32_t f2tf32(float x) {
    uint32_t u; asm("cvt.rn.tf32.f32 %0, %1;" : "=r"(u) : "f"(x)); return u;
}
__device__ __forceinline__ float tf32r(float x) {
    return __uint_as_float(f2tf32(x));
}

// ---------------- FPS: one block per batch, points register-resident -------------
__global__ __launch_bounds__(1024) void fps_kernel(const float* __restrict__ coords,
                                                   float* __restrict__ cent_out2)
{
    int b = blockIdx.x;
    int tid = threadIdx.x;
    float px[8], py[8], pz[8], pw[8], dmin[8];
#pragma unroll
    for (int i = 0; i < 8; i++) {
        int p = tid + i * 1024;
        const float* c = coords + ((size_t)b * PP + p) * 5;
        px[i] = c[1]; py[i] = c[2]; pz[i] = c[3]; pw[i] = c[4];
        dmin[i] = 1e30f;
    }
    __shared__ float last[4];
    __shared__ unsigned long long red[32];
    __shared__ int cur_s;
    int cur = 0;
    for (int m = 0; m < MM; m++) {
        if (tid == (cur & 1023)) {
            int i = cur >> 10;
            last[0] = px[i]; last[1] = py[i]; last[2] = pz[i]; last[3] = pw[i];
            float* o  = g_cent + ((size_t)b * MM + m) * 4;
            o[0] = px[i]; o[1] = py[i]; o[2] = pz[i]; o[3] = pw[i];
            float* o2 = cent_out2 + ((size_t)b * MM + m) * 4;
            o2[0] = px[i]; o2[1] = py[i]; o2[2] = pz[i]; o2[3] = pw[i];
        }
        __syncthreads();
        if (m == MM - 1) break;
        float lx = last[0], ly = last[1], lz = last[2], lw = last[3];
        unsigned long long best = 0ull;
#pragma unroll
        for (int i = 0; i < 8; i++) {
            float dx = __fsub_rn(px[i], lx);
            float dy = __fsub_rn(py[i], ly);
            float dz = __fsub_rn(pz[i], lz);
            float dw = __fsub_rn(pw[i], lw);
            float d = __fadd_rn(__fadd_rn(__fadd_rn(__fmul_rn(dx,dx), __fmul_rn(dy,dy)),
                                          __fmul_rn(dz,dz)), __fmul_rn(dw,dw));
            float dm = fminf(dmin[i], d);
            dmin[i] = dm;
            unsigned long long key = ((unsigned long long)__float_as_uint(dm) << 32)
                                   | (unsigned)(0x7FFFFFFF - (tid + i * 1024));
            if (key > best) best = key;
        }
        for (int off = 16; off; off >>= 1) {
            unsigned long long o = __shfl_down_sync(0xFFFFFFFFu, best, off);
            if (o > best) best = o;
        }
        if ((tid & 31) == 0) red[tid >> 5] = best;
        __syncthreads();
        if (tid < 32) {
            unsigned long long v = red[tid];
            for (int off = 16; off; off >>= 1) {
                unsigned long long o = __shfl_down_sync(0xFFFFFFFFu, v, off);
                if (o > v) v = o;
            }
            if (tid == 0) cur_s = 0x7FFFFFFF - (int)(v & 0xFFFFFFFFu);
        }
        __syncthreads();
        cur = cur_s;
    }
}

// ---------------- kNN: one block per centroid, keys in 64KB smem (R7 version) ------
__global__ __launch_bounds__(256) void knn_kernel(const float* __restrict__ coords,
                                                  int* __restrict__ knn)
{
    extern __shared__ unsigned long long keys[];
    int m = blockIdx.x, b = blockIdx.y;
    int tid = threadIdx.x;
    const float* c = g_cent + ((size_t)b * MM + m) * 4;
    float c0 = c[0], c1 = c[1], c2 = c[2], c3 = c[3];
    float cen2 = __fadd_rn(__fadd_rn(__fadd_rn(__fmul_rn(c0,c0), __fmul_rn(c1,c1)),
                                     __fmul_rn(c2,c2)), __fmul_rn(c3,c3));
    for (int p = tid; p < PP; p += 256) {
        const float* q = coords + ((size_t)b * PP + p) * 5;
        float x0 = q[1], x1 = q[2], x2 = q[3], x3 = q[4];
        float pts2 = __fadd_rn(__fadd_rn(__fadd_rn(__fmul_rn(x0,x0), __fmul_rn(x1,x1)),
                                         __fmul_rn(x2,x2)), __fmul_rn(x3,x3));
        float dot  = __fadd_rn(__fadd_rn(__fadd_rn(__fmul_rn(c0,x0), __fmul_rn(c1,x1)),
                                         __fmul_rn(c2,x2)), __fmul_rn(c3,x3));
        float d2 = __fsub_rn(__fadd_rn(cen2, pts2), __fmul_rn(2.0f, dot));
        unsigned u = __float_as_uint(d2);
        u = (u & 0x80000000u) ? ~u : (u | 0x80000000u);
        keys[p] = ((unsigned long long)u << 32) | (unsigned)p;
    }
    __syncthreads();
    __shared__ unsigned long long red[8];
    for (int k = 0; k < KNN; k++) {
        unsigned long long best = ~0ull;
        for (int p = tid; p < PP; p += 256) {
            unsigned long long v = keys[p];
            if (v < best) best = v;
        }
        for (int off = 16; off; off >>= 1) {
            unsigned long long o = __shfl_down_sync(0xFFFFFFFFu, best, off);
            if (o < best) best = o;
        }
        if ((tid & 31) == 0) red[tid >> 5] = best;
        __syncthreads();
        if (tid == 0) {
            unsigned long long v = red[0];
            for (int w = 1; w < 8; w++) if (red[w] < v) v = red[w];
            int idx = (int)(v & 0xFFFFFFFFu);
            knn[((size_t)b * MM + m) * KNN + k] = idx;
            keys[idx] = ~0ull;
        }
        __syncthreads();
    }
}

// ---------------- gather + layer1 (6 -> 256, relu): 8 rows per block --------------
__global__ __launch_bounds__(256) void gather_mlp1(const float* __restrict__ feats,
                                                   const float* __restrict__ W1,
                                                   const float* __restrict__ b1)
{
    int j = threadIdx.x;
    int rowbase = blockIdx.x * 8;
    float w[6];
#pragma unroll
    for (int t = 0; t < 6; t++) w[t] = W1[t * 256 + j];
    float bb = b1[j];
    __shared__ float fs[8][6];
    if (j < 48) {
        int r = j / 6, cidx = j % 6;
        int row = rowbase + r;
        int bidx = row >> 11;                       // row / (MM*KNN)
        int idx = g_knn[row];
        fs[r][cidx] = feats[((size_t)bidx * PP + idx) * 6 + cidx];
    }
    __syncthreads();
#pragma unroll
    for (int r = 0; r < 8; r++) {
        float acc = bb;
#pragma unroll
        for (int t = 0; t < 6; t++) acc = fmaf(fs[r][t], w[t], acc);
        g_bufA[(size_t)(rowbase + r) * 256 + j] = tf32r(fmaxf(acc, 0.f));
    }
}

// ---------------- all weight transposes in one kernel ------------------------------
#define TN_W2  (256*512)
#define TN_W3  (512*768)
#define TN_W44 (768*768)
#define TE1 TN_W2
#define TE2 (TE1 + TN_W3)
#define TE3 (TE2 + TN_W44)
#define TE4 (TE3 + TN_W44)
#define TE5 (TE4 + TN_W44)
__global__ __launch_bounds__(256) void transpose_all(
    const float* __restrict__ W2, const float* __restrict__ W3,
    const float* __restrict__ W4, const float* __restrict__ Wa1,
    const float* __restrict__ Wa2, float* __restrict__ Wt)
{
    int i = blockIdx.x * 256 + threadIdx.x;
    const float* W; float* dst; int N, K, j;
    if (i < TE1)      { j = i;       W = W2;  dst = Wt + OFF_W2T;  K = 256; N = 512; }
    else if (i < TE2) { j = i - TE1; W = W3;  dst = Wt + OFF_W3T;  K = 512; N = 768; }
    else if (i < TE3) { j = i - TE2; W = W4;  dst = Wt + OFF_W4T;  K = 768; N = 768; }
    else if (i < TE4) { j = i - TE3; W = Wa1; dst = Wt + OFF_WA1T; K = 768; N = 768; }
    else if (i < TE5) { j = i - TE4; W = Wa2; dst = Wt + OFF_WA2T; K = 768; N = 768; }
    else return;
    int k = j / N, n = j % N;
    dst[(size_t)n * K + k] = tf32r(W[j]);
}

// ================= tf32 mma.sync GEMM, 3-stage cp.async pipeline ===================
// C[Mr,N] = act(A[Mr,K] @ Bt[N,K]^T + bias)    (A, Bt already tf32-rounded fp32)
// POOL: instead of storing all rows, max-pool each 16-row group and store [Mr/16, N].
#define SPAD 36                      // smem row stride in words (conflict-free, 16B-OK)
#define STG_MAT (128 * SPAD * 4)     // 18432 B per matrix per stage
#define STG_BYTES (2 * STG_MAT)      // 36864 B per stage (A + B)
#define NSTAGE 3
#define GSMEM (NSTAGE * STG_BYTES)   // 110592 B

__device__ __forceinline__ void cp16(uint32_t saddr, const void* g) {
    asm volatile("cp.async.cg.shared.global [%0], [%1], 16;" :: "r"(saddr), "l"(g));
}

template<bool RELU, bool ROUND, bool POOL>
__global__ __launch_bounds__(256) void mma_gemm(
    const float* __restrict__ A, const float* __restrict__ Bt,
    const float* __restrict__ bias, float* __restrict__ C,
    int N, int K)
{
    extern __shared__ char dsm[];
    uint32_t sbase = (uint32_t)__cvta_generic_to_shared(dsm);
    int tid = threadIdx.x, wid = tid >> 5, lane = tid & 31;
    int gid = lane >> 2, tig = lane & 3;
    int bx = blockIdx.x, by = blockIdx.y;
    int m_base = (wid & 3) * 32;
    int n_base = (wid >> 2) * 64;

    const float* Ag = A  + (size_t)(by * 128) * K;
    const float* Bg = Bt + (size_t)(bx * 128) * K;

    int srow[4], sc4[4];
#pragma unroll
    for (int r = 0; r < 4; r++) {
        int id = tid + 256 * r;
        srow[r] = id >> 3;
        sc4[r]  = id & 7;
    }

    float acc[2][8][4];
#pragma unroll
    for (int mt = 0; mt < 2; mt++)
#pragma unroll
        for (int nt = 0; nt < 8; nt++)
#pragma unroll
            for (int j = 0; j < 4; j++) acc[mt][nt][j] = 0.f;

    int NC = K >> 5;

#pragma unroll
    for (int s = 0; s < 2; s++) {
        int kb = s << 5;
        uint32_t stb = sbase + s * STG_BYTES;
#pragma unroll
        for (int r = 0; r < 4; r++) {
            uint32_t doff = (uint32_t)(srow[r] * (SPAD * 4) + sc4[r] * 16);
            cp16(stb + doff,           Ag + (size_t)srow[r] * K + kb + sc4[r] * 4);
            cp16(stb + STG_MAT + doff, Bg + (size_t)srow[r] * K + kb + sc4[r] * 4);
        }
        asm volatile("cp.async.commit_group;" ::: "memory");
    }

    for (int c = 0; c < NC; c++) {
        asm volatile("cp.async.wait_group 1;" ::: "memory");
        __syncthreads();

        if (c + 2 < NC) {
            int kb = (c + 2) << 5;
            uint32_t stb = sbase + ((c + 2) % NSTAGE) * STG_BYTES;
#pragma unroll
            for (int r = 0; r < 4; r++) {
                uint32_t doff = (uint32_t)(srow[r] * (SPAD * 4) + sc4[r] * 16);
                cp16(stb + doff,           Ag + (size_t)srow[r] * K + kb + sc4[r] * 4);
                cp16(stb + STG_MAT + doff, Bg + (size_t)srow[r] * K + kb + sc4[r] * 4);
            }
        }
        asm volatile("cp.async.commit_group;" ::: "memory");

        const uint32_t* As = (const uint32_t*)(dsm + (c % NSTAGE) * STG_BYTES);
        const uint32_t* Bs = As + 128 * SPAD;

#pragma unroll
        for (int ks = 0; ks < 4; ks++) {
            int k0 = ks * 8;
            uint32_t af[2][4];
#pragma unroll
            for (int mt = 0; mt < 2; mt++) {
                int row = m_base + mt * 16 + gid;
                af[mt][0] = As[row * SPAD + k0 + tig];
                af[mt][1] = As[(row + 8) * SPAD + k0 + tig];
                af[mt][2] = As[row * SPAD + k0 + tig + 4];
                af[mt][3] = As[(row + 8) * SPAD + k0 + tig + 4];
            }
#pragma unroll
            for (int nt = 0; nt < 8; nt++) {
                int col = n_base + nt * 8 + gid;
                uint32_t b0 = Bs[col * SPAD + k0 + tig];
                uint32_t b1 = Bs[col * SPAD + k0 + tig + 4];
#pragma unroll
                for (int mt = 0; mt < 2; mt++) {
                    asm volatile(
                        "mma.sync.aligned.m16n8k8.row.col.f32.tf32.tf32.f32 "
                        "{%0,%1,%2,%3}, {%4,%5,%6,%7}, {%8,%9}, {%0,%1,%2,%3};"
                        : "+f"(acc[mt][nt][0]), "+f"(acc[mt][nt][1]),
                          "+f"(acc[mt][nt][2]), "+f"(acc[mt][nt][3])
                        : "r"(af[mt][0]), "r"(af[mt][1]), "r"(af[mt][2]), "r"(af[mt][3]),
                          "r"(b0), "r"(b1));
                }
            }
        }
    }

    // ---- epilogue ----
#pragma unroll
    for (int nt = 0; nt < 8; nt++) {
        int cg = bx * 128 + n_base + nt * 8 + 2 * tig;
        float bz0 = bias[cg], bz1 = bias[cg + 1];
#pragma unroll
        for (int mt = 0; mt < 2; mt++) {
            float v0 = acc[mt][nt][0] + bz0;
            float v1 = acc[mt][nt][1] + bz1;
            float v2 = acc[mt][nt][2] + bz0;
            float v3 = acc[mt][nt][3] + bz1;
            if (RELU) {
                v0 = fmaxf(v0, 0.f); v1 = fmaxf(v1, 0.f);
                v2 = fmaxf(v2, 0.f); v3 = fmaxf(v3, 0.f);
            }
            if (ROUND) {
                v0 = tf32r(v0); v1 = tf32r(v1);
                v2 = tf32r(v2); v3 = tf32r(v3);
            }
            if (POOL) {
                // 16-row pool group = warp rows [m_base+mt*16, +16): thread holds
                // rows gid and gid+8; reduce over gid lanes via shfl_xor 4/8/16.
                float m0 = fmaxf(v0, v2);
                float m1 = fmaxf(v1, v3);
#pragma unroll
                for (int off = 4; off <= 16; off <<= 1) {
                    m0 = fmaxf(m0, __shfl_xor_sync(0xFFFFFFFFu, m0, off));
                    m1 = fmaxf(m1, __shfl_xor_sync(0xFFFFFFFFu, m1, off));
                }
                if (gid == 0) {
                    int q = (by * 128 + m_base + mt * 16) >> 4;
                    *(float2*)(C + (size_t)q * N + cg) = make_float2(m0, m1);
                }
            } else {
                int rg = by * 128 + m_base + mt * 16 + gid;
                *(float2*)(C + (size_t)rg * N + cg)       = make_float2(v0, v1);
                *(float2*)(C + (size_t)(rg + 8) * N + cg) = make_float2(v2, v3);
            }
        }
    }
}

// ---------------- mask fill --------------------------------------------------------
__global__ void fill_mask(float* m)
{
    int i = blockIdx.x * 256 + threadIdx.x;
    if (i < QQ) m[i] = 1.0f;
}

// ---------------- launcher ---------------------------------------------------------
extern "C" void kernel_launch(void* const* d_in, const int* in_sizes, int n_in,
                              void* d_out, int out_size)
{
    const float* coords = (const float*)d_in[0];
    const float* feats  = (const float*)d_in[1];
    const float* W1 = (const float*)d_in[2];  const float* b1 = (const float*)d_in[3];
    const float* W2 = (const float*)d_in[4];  const float* b2 = (const float*)d_in[5];
    const float* W3 = (const float*)d_in[6];  const float* b3 = (const float*)d_in[7];
    const float* W4 = (const float*)d_in[8];  const float* b4 = (const float*)d_in[9];
    const float* Wa1 = (const float*)d_in[10]; const float* ba1 = (const float*)d_in[11];
    const float* Wa2 = (const float*)d_in[12]; const float* ba2 = (const float*)d_in[13];

    float* out     = (float*)d_out;
    float* tokens  = out;                               // [QQ, DD]
    float* centout = out + (size_t)QQ * DD;             // [QQ, 4]
    float* masks   = centout + (size_t)QQ * 4;          // [QQ]

    float *pA, *pB, *pPool, *pH, *pWt;
    int* pKnn;
    cudaGetSymbolAddress((void**)&pA, g_bufA);
    cudaGetSymbolAddress((void**)&pB, g_bufB);
    cudaGetSymbolAddress((void**)&pPool, g_pool);
    cudaGetSymbolAddress((void**)&pH, g_h);
    cudaGetSymbolAddress((void**)&pKnn, g_knn);
    cudaGetSymbolAddress((void**)&pWt, g_wt);

    // 1. FPS -> centroids
    fps_kernel<<<BB, 1024>>>(coords, centout);

    // 2. weight transposes (single kernel)
    transpose_all<<<(TE5 + 255) / 256, 256>>>(W2, W3, W4, Wa1, Wa2, pWt);

    // 3. kNN (64KB dynamic smem, scan version — proven fastest)
    cudaFuncSetAttribute(knn_kernel, cudaFuncAttributeMaxDynamicSharedMemorySize, PP * 8);
    knn_kernel<<<dim3(MM, BB), 256, PP * 8>>>(coords, pKnn);

    // 4. gather + layer1 (6 -> 256, relu, tf32-rounded) -> g_bufA
    gather_mlp1<<<RR / 8, 256>>>(feats, W1, b1);

    // 5. MLP chain on tensor cores; layer 4 fuses the max-pool into its epilogue
    cudaFuncSetAttribute((const void*)mma_gemm<true,  true,  false>, cudaFuncAttributeMaxDynamicSharedMemorySize, GSMEM);
    cudaFuncSetAttribute((const void*)mma_gemm<false, true,  true >, cudaFuncAttributeMaxDynamicSharedMemorySize, GSMEM);
    cudaFuncSetAttribute((const void*)mma_gemm<false, false, false>, cudaFuncAttributeMaxDynamicSharedMemorySize, GSMEM);
    mma_gemm<true,  true,  false><<<dim3(512 / 128, RR / 128), 256, GSMEM>>>(pA, pWt + OFF_W2T, b2, pB, 512, 256);
    mma_gemm<true,  true,  false><<<dim3(768 / 128, RR / 128), 256, GSMEM>>>(pB, pWt + OFF_W3T, b3, pA, 768, 512);
    // layer 4: output pooled directly into g_pool [QQ, 768]
    mma_gemm<false, true,  true ><<<dim3(768 / 128, RR / 128), 256, GSMEM>>>(pA, pWt + OFF_W4T, b4, pPool, 768, 768);

    // 6. attention MLP -> tokens
    mma_gemm<true,  true,  false><<<dim3(DD / 128, QQ / 128), 256, GSMEM>>>(pPool, pWt + OFF_WA1T, ba1, pH, 768, 768);
    mma_gemm<false, false, false><<<dim3(DD / 128, QQ / 128), 256, GSMEM>>>(pH, pWt + OFF_WA2T, ba2, tokens, 768, 768);

    // 7. masks
    fill_mask<<<(QQ + 255) / 256, 256>>>(masks);
}

// round 10
// speedup vs baseline: 1.2799x; 1.0321x over previous
#include <cuda_runtime.h>
#include <stdint.h>

#define BB 16
#define PP 8192
#define MM 128
#define KNN 16
#define DD 768
#define QQ (BB*MM)      // 2048 queries/tokens
#define RR (QQ*KNN)     // 32768 gathered rows

// ---------------- scratch (device globals; no allocation allowed) ----------------
__device__ float g_cent[QQ*4];
__device__ int   g_knn[RR];
__device__ float g_bufA[(size_t)RR*768];
__device__ float g_bufB[(size_t)RR*768];
__device__ float g_pool[(size_t)QQ*DD];
__device__ float g_h[(size_t)QQ*DD];
// transposed weights [N][K] (K-major so B operand is n-major/k-contiguous = "col" for mma)
#define OFF_W2T  0
#define OFF_W3T  (512*256)
#define OFF_W4T  (OFF_W3T + 768*512)
#define OFF_WA1T (OFF_W4T + 768*768)
#define OFF_WA2T (OFF_WA1T + 768*768)
__device__ float g_wt[OFF_WA2T + 768*768];

__device__ __forceinline__ uint32_t f2tf32(float x) {
    uint32_t u; asm("cvt.rn.tf32.f32 %0, %1;" : "=r"(u) : "f"(x)); return u;
}
__device__ __forceinline__ float tf32r(float x) {
    return __uint_as_float(f2tf32(x));
}

// ---------------- FPS: one block per batch, points register-resident -------------
__global__ __launch_bounds__(1024) void fps_kernel(const float* __restrict__ coords,
                                                   float* __restrict__ cent_out2)
{
    int b = blockIdx.x;
    int tid = threadIdx.x;
    float px[8], py[8], pz[8], pw[8], dmin[8];
#pragma unroll
    for (int i = 0; i < 8; i++) {
        int p = tid + i * 1024;
        const float* c = coords + ((size_t)b * PP + p) * 5;
        px[i] = c[1]; py[i] = c[2]; pz[i] = c[3]; pw[i] = c[4];
        dmin[i] = 1e30f;
    }
    __shared__ float last[4];
    __shared__ unsigned long long red[32];
    __shared__ int cur_s;
    int cur = 0;
    for (int m = 0; m < MM; m++) {
        if (tid == (cur & 1023)) {
            int i = cur >> 10;
            last[0] = px[i]; last[1] = py[i]; last[2] = pz[i]; last[3] = pw[i];
            float* o  = g_cent + ((size_t)b * MM + m) * 4;
            o[0] = px[i]; o[1] = py[i]; o[2] = pz[i]; o[3] = pw[i];
            float* o2 = cent_out2 + ((size_t)b * MM + m) * 4;
            o2[0] = px[i]; o2[1] = py[i]; o2[2] = pz[i]; o2[3] = pw[i];
        }
        __syncthreads();
        if (m == MM - 1) break;
        float lx = last[0], ly = last[1], lz = last[2], lw = last[3];
        unsigned long long best = 0ull;
#pragma unroll
        for (int i = 0; i < 8; i++) {
            float dx = __fsub_rn(px[i], lx);
            float dy = __fsub_rn(py[i], ly);
            float dz = __fsub_rn(pz[i], lz);
            float dw = __fsub_rn(pw[i], lw);
            float d = __fadd_rn(__fadd_rn(__fadd_rn(__fmul_rn(dx,dx), __fmul_rn(dy,dy)),
                                          __fmul_rn(dz,dz)), __fmul_rn(dw,dw));
            float dm = fminf(dmin[i], d);
            dmin[i] = dm;
            unsigned long long key = ((unsigned long long)__float_as_uint(dm) << 32)
                                   | (unsigned)(0x7FFFFFFF - (tid + i * 1024));
            if (key > best) best = key;
        }
        for (int off = 16; off; off >>= 1) {
            unsigned long long o = __shfl_down_sync(0xFFFFFFFFu, best, off);
            if (o > best) best = o;
        }
        if ((tid & 31) == 0) red[tid >> 5] = best;
        __syncthreads();
        if (tid < 32) {
            unsigned long long v = red[tid];
            for (int off = 16; off; off >>= 1) {
                unsigned long long o = __shfl_down_sync(0xFFFFFFFFu, v, off);
                if (o > v) v = o;
            }
            if (tid == 0) cur_s = 0x7FFFFFFF - (int)(v & 0xFFFFFFFFu);
        }
        __syncthreads();
        cur = cur_s;
    }
}

// ---------------- kNN: tournament selection ----------------------------------------
// Phase 1 identical key construction (bit-exact distances). Keys are thread-private
// (slot p ≡ tid mod 256) so only the owner reads/writes them. Phase 2: register min
// per thread + block reduce; unique winner (index in low bits) rescans its 32 keys.
__global__ __launch_bounds__(256) void knn_kernel(const float* __restrict__ coords,
                                                  int* __restrict__ knn)
{
    extern __shared__ unsigned long long keys[];   // PP entries
    __shared__ unsigned long long red[8];
    __shared__ unsigned long long win_s;
    int m = blockIdx.x, b = blockIdx.y;
    int tid = threadIdx.x;
    const float* c = g_cent + ((size_t)b * MM + m) * 4;
    float c0 = c[0], c1 = c[1], c2 = c[2], c3 = c[3];
    float cen2 = __fadd_rn(__fadd_rn(__fadd_rn(__fmul_rn(c0,c0), __fmul_rn(c1,c1)),
                                     __fmul_rn(c2,c2)), __fmul_rn(c3,c3));
    unsigned long long mymin = ~0ull;
#pragma unroll 4
    for (int it = 0; it < PP / 256; it++) {
        int p = tid + it * 256;
        const float* q = coords + ((size_t)b * PP + p) * 5;
        float x0 = q[1], x1 = q[2], x2 = q[3], x3 = q[4];
        float pts2 = __fadd_rn(__fadd_rn(__fadd_rn(__fmul_rn(x0,x0), __fmul_rn(x1,x1)),
                                         __fmul_rn(x2,x2)), __fmul_rn(x3,x3));
        float dot  = __fadd_rn(__fadd_rn(__fadd_rn(__fmul_rn(c0,x0), __fmul_rn(c1,x1)),
                                         __fmul_rn(c2,x2)), __fmul_rn(c3,x3));
        float d2 = __fsub_rn(__fadd_rn(cen2, pts2), __fmul_rn(2.0f, dot));
        unsigned u = __float_as_uint(d2);
        u = (u & 0x80000000u) ? ~u : (u | 0x80000000u);   // order-preserving map
        unsigned long long key = ((unsigned long long)u << 32) | (unsigned)p;
        keys[p] = key;
        if (key < mymin) mymin = key;
    }
    int* outp = knn + ((size_t)b * MM + m) * KNN;
    for (int k = 0; k < KNN; k++) {
        unsigned long long v = mymin;
        for (int off = 16; off; off >>= 1) {
            unsigned long long o = __shfl_down_sync(0xFFFFFFFFu, v, off);
            if (o < v) v = o;
        }
        if ((tid & 31) == 0) red[tid >> 5] = v;
        __syncthreads();
        if (tid == 0) {
            unsigned long long w = red[0];
#pragma unroll
            for (int j = 1; j < 8; j++) if (red[j] < w) w = red[j];
            win_s = w;
            outp[k] = (int)(w & 0xFFFFFFFFu);
        }
        __syncthreads();
        if (mymin == win_s) {           // unique winner (index embedded in key)
            keys[(unsigned)(mymin & 0xFFFFFFFFu)] = ~0ull;
            unsigned long long nm = ~0ull;
#pragma unroll 4
            for (int it = 0; it < PP / 256; it++) {
                unsigned long long t = keys[tid + it * 256];
                if (t < nm) nm = t;
            }
            mymin = nm;
        }
    }
}

// ---------------- gather + layer1 (6 -> 256, relu): 8 rows per block --------------
__global__ __launch_bounds__(256) void gather_mlp1(const float* __restrict__ feats,
                                                   const float* __restrict__ W1,
                                                   const float* __restrict__ b1)
{
    int j = threadIdx.x;
    int rowbase = blockIdx.x * 8;
    float w[6];
#pragma unroll
    for (int t = 0; t < 6; t++) w[t] = W1[t * 256 + j];
    float bb = b1[j];
    __shared__ float fs[8][6];
    if (j < 48) {
        int r = j / 6, cidx = j % 6;
        int row = rowbase + r;
        int bidx = row >> 11;                       // row / (MM*KNN)
        int idx = g_knn[row];
        fs[r][cidx] = feats[((size_t)bidx * PP + idx) * 6 + cidx];
    }
    __syncthreads();
#pragma unroll
    for (int r = 0; r < 8; r++) {
        float acc = bb;
#pragma unroll
        for (int t = 0; t < 6; t++) acc = fmaf(fs[r][t], w[t], acc);
        g_bufA[(size_t)(rowbase + r) * 256 + j] = tf32r(fmaxf(acc, 0.f));
    }
}

// ---------------- all weight transposes in one kernel ------------------------------
#define TN_W2  (256*512)
#define TN_W3  (512*768)
#define TN_W44 (768*768)
#define TE1 TN_W2
#define TE2 (TE1 + TN_W3)
#define TE3 (TE2 + TN_W44)
#define TE4 (TE3 + TN_W44)
#define TE5 (TE4 + TN_W44)
__global__ __launch_bounds__(256) void transpose_all(
    const float* __restrict__ W2, const float* __restrict__ W3,
    const float* __restrict__ W4, const float* __restrict__ Wa1,
    const float* __restrict__ Wa2, float* __restrict__ Wt)
{
    int i = blockIdx.x * 256 + threadIdx.x;
    const float* W; float* dst; int N, K, j;
    if (i < TE1)      { j = i;       W = W2;  dst = Wt + OFF_W2T;  K = 256; N = 512; }
    else if (i < TE2) { j = i - TE1; W = W3;  dst = Wt + OFF_W3T;  K = 512; N = 768; }
    else if (i < TE3) { j = i - TE2; W = W4;  dst = Wt + OFF_W4T;  K = 768; N = 768; }
    else if (i < TE4) { j = i - TE3; W = Wa1; dst = Wt + OFF_WA1T; K = 768; N = 768; }
    else if (i < TE5) { j = i - TE4; W = Wa2; dst = Wt + OFF_WA2T; K = 768; N = 768; }
    else return;
    int k = j / N, n = j % N;
    dst[(size_t)n * K + k] = tf32r(W[j]);
}

// ================= tf32 mma.sync GEMM, 3-stage cp.async pipeline ===================
// C[Mr,N] = act(A[Mr,K] @ Bt[N,K]^T + bias)    (A, Bt already tf32-rounded fp32)
// POOL: instead of storing all rows, max-pool each 16-row group and store [Mr/16, N].
#define SPAD 36                      // smem row stride in words (conflict-free, 16B-OK)
#define STG_MAT (128 * SPAD * 4)     // 18432 B per matrix per stage
#define STG_BYTES (2 * STG_MAT)      // 36864 B per stage (A + B)
#define NSTAGE 3
#define GSMEM (NSTAGE * STG_BYTES)   // 110592 B

__device__ __forceinline__ void cp16(uint32_t saddr, const void* g) {
    asm volatile("cp.async.cg.shared.global [%0], [%1], 16;" :: "r"(saddr), "l"(g));
}

template<bool RELU, bool ROUND, bool POOL>
__global__ __launch_bounds__(256, 2) void mma_gemm(
    const float* __restrict__ A, const float* __restrict__ Bt,
    const float* __restrict__ bias, float* __restrict__ C,
    int N, int K)
{
    extern __shared__ char dsm[];
    uint32_t sbase = (uint32_t)__cvta_generic_to_shared(dsm);
    int tid = threadIdx.x, wid = tid >> 5, lane = tid & 31;
    int gid = lane >> 2, tig = lane & 3;
    int bx = blockIdx.x, by = blockIdx.y;
    int m_base = (wid & 3) * 32;
    int n_base = (wid >> 2) * 64;

    const float* Ag = A  + (size_t)(by * 128) * K;
    const float* Bg = Bt + (size_t)(bx * 128) * K;

    int srow[4], sc4[4];
#pragma unroll
    for (int r = 0; r < 4; r++) {
        int id = tid + 256 * r;
        srow[r] = id >> 3;
        sc4[r]  = id & 7;
    }

    float acc[2][8][4];
#pragma unroll
    for (int mt = 0; mt < 2; mt++)
#pragma unroll
        for (int nt = 0; nt < 8; nt++)
#pragma unroll
            for (int j = 0; j < 4; j++) acc[mt][nt][j] = 0.f;

    int NC = K >> 5;

#pragma unroll
    for (int s = 0; s < 2; s++) {
        int kb = s << 5;
        uint32_t stb = sbase + s * STG_BYTES;
#pragma unroll
        for (int r = 0; r < 4; r++) {
            uint32_t doff = (uint32_t)(srow[r] * (SPAD * 4) + sc4[r] * 16);
            cp16(stb + doff,           Ag + (size_t)srow[r] * K + kb + sc4[r] * 4);
            cp16(stb + STG_MAT + doff, Bg + (size_t)srow[r] * K + kb + sc4[r] * 4);
        }
        asm volatile("cp.async.commit_group;" ::: "memory");
    }

    for (int c = 0; c < NC; c++) {
        asm volatile("cp.async.wait_group 1;" ::: "memory");
        __syncthreads();

        if (c + 2 < NC) {
            int kb = (c + 2) << 5;
            uint32_t stb = sbase + ((c + 2) % NSTAGE) * STG_BYTES;
#pragma unroll
            for (int r = 0; r < 4; r++) {
                uint32_t doff = (uint32_t)(srow[r] * (SPAD * 4) + sc4[r] * 16);
                cp16(stb + doff,           Ag + (size_t)srow[r] * K + kb + sc4[r] * 4);
                cp16(stb + STG_MAT + doff, Bg + (size_t)srow[r] * K + kb + sc4[r] * 4);
            }
        }
        asm volatile("cp.async.commit_group;" ::: "memory");

        const uint32_t* As = (const uint32_t*)(dsm + (c % NSTAGE) * STG_BYTES);
        const uint32_t* Bs = As + 128 * SPAD;

#pragma unroll
        for (int ks = 0; ks < 4; ks++) {
            int k0 = ks * 8;
            uint32_t af[2][4];
#pragma unroll
            for (int mt = 0; mt < 2; mt++) {
                int row = m_base + mt * 16 + gid;
                af[mt][0] = As[row * SPAD + k0 + tig];
                af[mt][1] = As[(row + 8) * SPAD + k0 + tig];
                af[mt][2] = As[row * SPAD + k0 + tig + 4];
                af[mt][3] = As[(row + 8) * SPAD + k0 + tig + 4];
            }
#pragma unroll
            for (int nt = 0; nt < 8; nt++) {
                int col = n_base + nt * 8 + gid;
                uint32_t b0 = Bs[col * SPAD + k0 + tig];
                uint32_t b1 = Bs[col * SPAD + k0 + tig + 4];
#pragma unroll
                for (int mt = 0; mt < 2; mt++) {
                    asm volatile(
                        "mma.sync.aligned.m16n8k8.row.col.f32.tf32.tf32.f32 "
                        "{%0,%1,%2,%3}, {%4,%5,%6,%7}, {%8,%9}, {%0,%1,%2,%3};"
                        : "+f"(acc[mt][nt][0]), "+f"(acc[mt][nt][1]),
                          "+f"(acc[mt][nt][2]), "+f"(acc[mt][nt][3])
                        : "r"(af[mt][0]), "r"(af[mt][1]), "r"(af[mt][2]), "r"(af[mt][3]),
                          "r"(b0), "r"(b1));
                }
            }
        }
    }

    // ---- epilogue ----
#pragma unroll
    for (int nt = 0; nt < 8; nt++) {
        int cg = bx * 128 + n_base + nt * 8 + 2 * tig;
        float bz0 = bias[cg], bz1 = bias[cg + 1];
#pragma unroll
        for (int mt = 0; mt < 2; mt++) {
            float v0 = acc[mt][nt][0] + bz0;
            float v1 = acc[mt][nt][1] + bz1;
            float v2 = acc[mt][nt][2] + bz0;
            float v3 = acc[mt][nt][3] + bz1;
            if (RELU) {
                v0 = fmaxf(v0, 0.f); v1 = fmaxf(v1, 0.f);
                v2 = fmaxf(v2, 0.f); v3 = fmaxf(v3, 0.f);
            }
            if (ROUND) {
                v0 = tf32r(v0); v1 = tf32r(v1);
                v2 = tf32r(v2); v3 = tf32r(v3);
            }
            if (POOL) {
                float m0 = fmaxf(v0, v2);
                float m1 = fmaxf(v1, v3);
#pragma unroll
                for (int off = 4; off <= 16; off <<= 1) {
                    m0 = fmaxf(m0, __shfl_xor_sync(0xFFFFFFFFu, m0, off));
                    m1 = fmaxf(m1, __shfl_xor_sync(0xFFFFFFFFu, m1, off));
                }
                if (gid == 0) {
                    int q = (by * 128 + m_base + mt * 16) >> 4;
                    *(float2*)(C + (size_t)q * N + cg) = make_float2(m0, m1);
                }
            } else {
                int rg = by * 128 + m_base + mt * 16 + gid;
                *(float2*)(C + (size_t)rg * N + cg)       = make_float2(v0, v1);
                *(float2*)(C + (size_t)(rg + 8) * N + cg) = make_float2(v2, v3);
            }
        }
    }
}

// ---------------- mask fill --------------------------------------------------------
__global__ void fill_mask(float* m)
{
    int i = blockIdx.x * 256 + threadIdx.x;
    if (i < QQ) m[i] = 1.0f;
}

// ---------------- launcher ---------------------------------------------------------
extern "C" void kernel_launch(void* const* d_in, const int* in_sizes, int n_in,
                              void* d_out, int out_size)
{
    const float* coords = (const float*)d_in[0];
    const float* feats  = (const float*)d_in[1];
    const float* W1 = (const float*)d_in[2];  const float* b1 = (const float*)d_in[3];
    const float* W2 = (const float*)d_in[4];  const float* b2 = (const float*)d_in[5];
    const float* W3 = (const float*)d_in[6];  const float* b3 = (const float*)d_in[7];
    const float* W4 = (const float*)d_in[8];  const float* b4 = (const float*)d_in[9];
    const float* Wa1 = (const float*)d_in[10]; const float* ba1 = (const float*)d_in[11];
    const float* Wa2 = (const float*)d_in[12]; const float* ba2 = (const float*)d_in[13];

    float* out     = (float*)d_out;
    float* tokens  = out;                               // [QQ, DD]
    float* centout = out + (size_t)QQ * DD;             // [QQ, 4]
    float* masks   = centout + (size_t)QQ * 4;          // [QQ]

    float *pA, *pB, *pPool, *pH, *pWt;
    int* pKnn;
    cudaGetSymbolAddress((void**)&pA, g_bufA);
    cudaGetSymbolAddress((void**)&pB, g_bufB);
    cudaGetSymbolAddress((void**)&pPool, g_pool);
    cudaGetSymbolAddress((void**)&pH, g_h);
    cudaGetSymbolAddress((void**)&pKnn, g_knn);
    cudaGetSymbolAddress((void**)&pWt, g_wt);

    // 1. FPS -> centroids
    fps_kernel<<<BB, 1024>>>(coords, centout);

    // 2. weight transposes (single kernel)
    transpose_all<<<(TE5 + 255) / 256, 256>>>(W2, W3, W4, Wa1, Wa2, pWt);

    // 3. kNN (64KB dynamic smem, tournament selection)
    cudaFuncSetAttribute(knn_kernel, cudaFuncAttributeMaxDynamicSharedMemorySize, PP * 8);
    knn_kernel<<<dim3(MM, BB), 256, PP * 8>>>(coords, pKnn);

    // 4. gather + layer1 (6 -> 256, relu, tf32-rounded) -> g_bufA
    gather_mlp1<<<RR / 8, 256>>>(feats, W1, b1);

    // 5. MLP chain on tensor cores; layer 4 fuses the max-pool into its epilogue
    cudaFuncSetAttribute((const void*)mma_gemm<true,  true,  false>, cudaFuncAttributeMaxDynamicSharedMemorySize, GSMEM);
    cudaFuncSetAttribute((const void*)mma_gemm<false, true,  true >, cudaFuncAttributeMaxDynamicSharedMemorySize, GSMEM);
    cudaFuncSetAttribute((const void*)mma_gemm<false, false, false>, cudaFuncAttributeMaxDynamicSharedMemorySize, GSMEM);
    mma_gemm<true,  true,  false><<<dim3(512 / 128, RR / 128), 256, GSMEM>>>(pA, pWt + OFF_W2T, b2, pB, 512, 256);
    mma_gemm<true,  true,  false><<<dim3(768 / 128, RR / 128), 256, GSMEM>>>(pB, pWt + OFF_W3T, b3, pA, 768, 512);
    // layer 4: output pooled directly into g_pool [QQ, 768]
    mma_gemm<false, true,  true ><<<dim3(768 / 128, RR / 128), 256, GSMEM>>>(pA, pWt + OFF_W4T, b4, pPool, 768, 768);

    // 6. attention MLP -> tokens
    mma_gemm<true,  true,  false><<<dim3(DD / 128, QQ / 128), 256, GSMEM>>>(pPool, pWt + OFF_WA1T, ba1, pH, 768, 768);
    mma_gemm<false, false, false><<<dim3(DD / 128, QQ / 128), 256, GSMEM>>>(pH, pWt + OFF_WA2T, ba2, tokens, 768, 768);

    // 7. masks
    fill_mask<<<(QQ + 255) / 256, 256>>>(masks);
}

// round 11
// speedup vs baseline: 1.7954x; 1.4028x over previous
#include <cuda_runtime.h>
#include <cuda_fp16.h>
#include <stdint.h>

#define BB 16
#define PP 8192
#define MM 128
#define KNN 16
#define DD 768
#define QQ (BB*MM)      // 2048 queries/tokens
#define RR (QQ*KNN)     // 32768 gathered rows

// ---------------- scratch (device globals; no allocation allowed) ----------------
__device__ float  g_cent[QQ*4];
__device__ int    g_knn[RR];
__device__ __half g_bufA[(size_t)RR*768];
__device__ __half g_bufB[(size_t)RR*768];
__device__ __half g_pool[(size_t)QQ*DD];
__device__ __half g_h[(size_t)QQ*DD];
// transposed weights [N][K] (K-major so B operand is k-contiguous = "col" for mma)
#define OFF_W2T  0
#define OFF_W3T  (512*256)
#define OFF_W4T  (OFF_W3T + 768*512)
#define OFF_WA1T (OFF_W4T + 768*768)
#define OFF_WA2T (OFF_WA1T + 768*768)
__device__ __half g_wt[OFF_WA2T + 768*768];

// ---------------- FPS: one block per batch, points register-resident -------------
__global__ __launch_bounds__(1024) void fps_kernel(const float* __restrict__ coords,
                                                   float* __restrict__ cent_out2)
{
    int b = blockIdx.x;
    int tid = threadIdx.x;
    float px[8], py[8], pz[8], pw[8], dmin[8];
#pragma unroll
    for (int i = 0; i < 8; i++) {
        int p = tid + i * 1024;
        const float* c = coords + ((size_t)b * PP + p) * 5;
        px[i] = c[1]; py[i] = c[2]; pz[i] = c[3]; pw[i] = c[4];
        dmin[i] = 1e30f;
    }
    __shared__ float last[4];
    __shared__ unsigned long long red[32];
    __shared__ int cur_s;
    int cur = 0;
    for (int m = 0; m < MM; m++) {
        if (tid == (cur & 1023)) {
            int i = cur >> 10;
            last[0] = px[i]; last[1] = py[i]; last[2] = pz[i]; last[3] = pw[i];
            float* o  = g_cent + ((size_t)b * MM + m) * 4;
            o[0] = px[i]; o[1] = py[i]; o[2] = pz[i]; o[3] = pw[i];
            float* o2 = cent_out2 + ((size_t)b * MM + m) * 4;
            o2[0] = px[i]; o2[1] = py[i]; o2[2] = pz[i]; o2[3] = pw[i];
        }
        __syncthreads();
        if (m == MM - 1) break;
        float lx = last[0], ly = last[1], lz = last[2], lw = last[3];
        unsigned long long best = 0ull;
#pragma unroll
        for (int i = 0; i < 8; i++) {
            float dx = __fsub_rn(px[i], lx);
            float dy = __fsub_rn(py[i], ly);
            float dz = __fsub_rn(pz[i], lz);
            float dw = __fsub_rn(pw[i], lw);
            float d = __fadd_rn(__fadd_rn(__fadd_rn(__fmul_rn(dx,dx), __fmul_rn(dy,dy)),
                                          __fmul_rn(dz,dz)), __fmul_rn(dw,dw));
            float dm = fminf(dmin[i], d);
            dmin[i] = dm;
            unsigned long long key = ((unsigned long long)__float_as_uint(dm) << 32)
                                   | (unsigned)(0x7FFFFFFF - (tid + i * 1024));
            if (key > best) best = key;
        }
        for (int off = 16; off; off >>= 1) {
            unsigned long long o = __shfl_down_sync(0xFFFFFFFFu, best, off);
            if (o > best) best = o;
        }
        if ((tid & 31) == 0) red[tid >> 5] = best;
        __syncthreads();
        if (tid < 32) {
            unsigned long long v = red[tid];
            for (int off = 16; off; off >>= 1) {
                unsigned long long o = __shfl_down_sync(0xFFFFFFFFu, v, off);
                if (o > v) v = o;
            }
            if (tid == 0) cur_s = 0x7FFFFFFF - (int)(v & 0xFFFFFFFFu);
        }
        __syncthreads();
        cur = cur_s;
    }
}

// ---------------- kNN: tournament selection (R10 version, bit-exact picks) --------
__global__ __launch_bounds__(256) void knn_kernel(const float* __restrict__ coords,
                                                  int* __restrict__ knn)
{
    extern __shared__ unsigned long long keys[];   // PP entries
    __shared__ unsigned long long red[8];
    __shared__ unsigned long long win_s;
    int m = blockIdx.x, b = blockIdx.y;
    int tid = threadIdx.x;
    const float* c = g_cent + ((size_t)b * MM + m) * 4;
    float c0 = c[0], c1 = c[1], c2 = c[2], c3 = c[3];
    float cen2 = __fadd_rn(__fadd_rn(__fadd_rn(__fmul_rn(c0,c0), __fmul_rn(c1,c1)),
                                     __fmul_rn(c2,c2)), __fmul_rn(c3,c3));
    unsigned long long mymin = ~0ull;
#pragma unroll 4
    for (int it = 0; it < PP / 256; it++) {
        int p = tid + it * 256;
        const float* q = coords + ((size_t)b * PP + p) * 5;
        float x0 = q[1], x1 = q[2], x2 = q[3], x3 = q[4];
        float pts2 = __fadd_rn(__fadd_rn(__fadd_rn(__fmul_rn(x0,x0), __fmul_rn(x1,x1)),
                                         __fmul_rn(x2,x2)), __fmul_rn(x3,x3));
        float dot  = __fadd_rn(__fadd_rn(__fadd_rn(__fmul_rn(c0,x0), __fmul_rn(c1,x1)),
                                         __fmul_rn(c2,x2)), __fmul_rn(c3,x3));
        float d2 = __fsub_rn(__fadd_rn(cen2, pts2), __fmul_rn(2.0f, dot));
        unsigned u = __float_as_uint(d2);
        u = (u & 0x80000000u) ? ~u : (u | 0x80000000u);   // order-preserving map
        unsigned long long key = ((unsigned long long)u << 32) | (unsigned)p;
        keys[p] = key;
        if (key < mymin) mymin = key;
    }
    int* outp = knn + ((size_t)b * MM + m) * KNN;
    for (int k = 0; k < KNN; k++) {
        unsigned long long v = mymin;
        for (int off = 16; off; off >>= 1) {
            unsigned long long o = __shfl_down_sync(0xFFFFFFFFu, v, off);
            if (o < v) v = o;
        }
        if ((tid & 31) == 0) red[tid >> 5] = v;
        __syncthreads();
        if (tid == 0) {
            unsigned long long w = red[0];
#pragma unroll
            for (int j = 1; j < 8; j++) if (red[j] < w) w = red[j];
            win_s = w;
            outp[k] = (int)(w & 0xFFFFFFFFu);
        }
        __syncthreads();
        if (mymin == win_s) {
            keys[(unsigned)(mymin & 0xFFFFFFFFu)] = ~0ull;
            unsigned long long nm = ~0ull;
#pragma unroll 4
            for (int it = 0; it < PP / 256; it++) {
                unsigned long long t = keys[tid + it * 256];
                if (t < nm) nm = t;
            }
            mymin = nm;
        }
    }
}

// ---------------- gather + layer1 (6 -> 256, relu): 8 rows per block, fp16 out ----
__global__ __launch_bounds__(256) void gather_mlp1(const float* __restrict__ feats,
                                                   const float* __restrict__ W1,
                                                   const float* __restrict__ b1)
{
    int j = threadIdx.x;
    int rowbase = blockIdx.x * 8;
    float w[6];
#pragma unroll
    for (int t = 0; t < 6; t++) w[t] = W1[t * 256 + j];
    float bb = b1[j];
    __shared__ float fs[8][6];
    if (j < 48) {
        int r = j / 6, cidx = j % 6;
        int row = rowbase + r;
        int bidx = row >> 11;                       // row / (MM*KNN)
        int idx = g_knn[row];
        fs[r][cidx] = feats[((size_t)bidx * PP + idx) * 6 + cidx];
    }
    __syncthreads();
#pragma unroll
    for (int r = 0; r < 8; r++) {
        float acc = bb;
#pragma unroll
        for (int t = 0; t < 6; t++) acc = fmaf(fs[r][t], w[t], acc);
        g_bufA[(size_t)(rowbase + r) * 256 + j] = __float2half_rn(fmaxf(acc, 0.f));
    }
}

// ---------------- all weight transposes in one kernel (fp16 out) -------------------
#define TN_W2  (256*512)
#define TN_W3  (512*768)
#define TN_W44 (768*768)
#define TE1 TN_W2
#define TE2 (TE1 + TN_W3)
#define TE3 (TE2 + TN_W44)
#define TE4 (TE3 + TN_W44)
#define TE5 (TE4 + TN_W44)
__global__ __launch_bounds__(256) void transpose_all(
    const float* __restrict__ W2, const float* __restrict__ W3,
    const float* __restrict__ W4, const float* __restrict__ Wa1,
    const float* __restrict__ Wa2, __half* __restrict__ Wt)
{
    int i = blockIdx.x * 256 + threadIdx.x;
    const float* W; __half* dst; int N, K, j;
    if (i < TE1)      { j = i;       W = W2;  dst = Wt + OFF_W2T;  K = 256; N = 512; }
    else if (i < TE2) { j = i - TE1; W = W3;  dst = Wt + OFF_W3T;  K = 512; N = 768; }
    else if (i < TE3) { j = i - TE2; W = W4;  dst = Wt + OFF_W4T;  K = 768; N = 768; }
    else if (i < TE4) { j = i - TE3; W = Wa1; dst = Wt + OFF_WA1T; K = 768; N = 768; }
    else if (i < TE5) { j = i - TE4; W = Wa2; dst = Wt + OFF_WA2T; K = 768; N = 768; }
    else return;
    int k = j / N, n = j % N;
    dst[(size_t)n * K + k] = __float2half_rn(W[j]);
}

// ================= fp16 mma.sync m16n8k16 GEMM, 3-stage cp.async pipeline ==========
// C[Mr,N] = act(A[Mr,K] @ Bt[N,K]^T + bias)    (A, Bt fp16; accumulate fp32)
// CTA tile 128x128. K staged in chunks of 64 halves (128B/row). 8 warps: 4(m)x2(n).
// POOL: max-pool each 16-row group in the epilogue, store [Mr/16, N].
#define SPAD 36                      // smem row stride in 32-bit words (=72 halves)
#define STG_MAT (128 * SPAD * 4)     // 18432 B per matrix per stage
#define STG_BYTES (2 * STG_MAT)      // 36864 B per stage (A + B)
#define NSTAGE 3
#define GSMEM (NSTAGE * STG_BYTES)   // 110592 B

__device__ __forceinline__ void cp16(uint32_t saddr, const void* g) {
    asm volatile("cp.async.cg.shared.global [%0], [%1], 16;" :: "r"(saddr), "l"(g));
}

template<bool RELU, bool POOL, bool HALF_OUT>
__global__ __launch_bounds__(256, 2) void mma_gemm(
    const __half* __restrict__ A, const __half* __restrict__ Bt,
    const float* __restrict__ bias, void* __restrict__ Cv,
    int N, int K)
{
    extern __shared__ char dsm[];
    uint32_t sbase = (uint32_t)__cvta_generic_to_shared(dsm);
    int tid = threadIdx.x, wid = tid >> 5, lane = tid & 31;
    int gid = lane >> 2, tig = lane & 3;
    int bx = blockIdx.x, by = blockIdx.y;
    int m_base = (wid & 3) * 32;
    int n_base = (wid >> 2) * 64;

    const __half* Ag = A  + (size_t)(by * 128) * K;
    const __half* Bg = Bt + (size_t)(bx * 128) * K;

    // staging: per chunk per matrix 128 rows x 128B = 1024 x 16B; 4 per thread
    int srow[4], sq[4];
#pragma unroll
    for (int r = 0; r < 4; r++) {
        int id = tid + 256 * r;
        srow[r] = id >> 3;          // 0..127
        sq[r]   = id & 7;           // 16B unit within row
    }

    float acc[2][8][4];
#pragma unroll
    for (int mt = 0; mt < 2; mt++)
#pragma unroll
        for (int nt = 0; nt < 8; nt++)
#pragma unroll
            for (int j = 0; j < 4; j++) acc[mt][nt][j] = 0.f;

    int NC = K >> 6;   // chunks of 64 halves

#pragma unroll
    for (int s = 0; s < 2; s++) {
        int kb = s << 6;
        uint32_t stb = sbase + s * STG_BYTES;
#pragma unroll
        for (int r = 0; r < 4; r++) {
            uint32_t doff = (uint32_t)(srow[r] * (SPAD * 4) + sq[r] * 16);
            cp16(stb + doff,           Ag + (size_t)srow[r] * K + kb + sq[r] * 8);
            cp16(stb + STG_MAT + doff, Bg + (size_t)srow[r] * K + kb + sq[r] * 8);
        }
        asm volatile("cp.async.commit_group;" ::: "memory");
    }

    for (int c = 0; c < NC; c++) {
        asm volatile("cp.async.wait_group 1;" ::: "memory");
        __syncthreads();

        if (c + 2 < NC) {
            int kb = (c + 2) << 6;
            uint32_t stb = sbase + ((c + 2) % NSTAGE) * STG_BYTES;
#pragma unroll
            for (int r = 0; r < 4; r++) {
                uint32_t doff = (uint32_t)(srow[r] * (SPAD * 4) + sq[r] * 16);
                cp16(stb + doff,           Ag + (size_t)srow[r] * K + kb + sq[r] * 8);
                cp16(stb + STG_MAT + doff, Bg + (size_t)srow[r] * K + kb + sq[r] * 8);
            }
        }
        asm volatile("cp.async.commit_group;" ::: "memory");

        const uint32_t* As = (const uint32_t*)(dsm + (c % NSTAGE) * STG_BYTES);
        const uint32_t* Bs = As + 128 * SPAD;

        // 4 ks steps of K=16 halves; word offset k0w = ks*8 (8 words = 16 halves)
#pragma unroll
        for (int ks = 0; ks < 4; ks++) {
            int k0 = ks * 8;
            uint32_t af[2][4];
#pragma unroll
            for (int mt = 0; mt < 2; mt++) {
                int row = m_base + mt * 16 + gid;
                af[mt][0] = As[row * SPAD + k0 + tig];          // A[row][2tig..2tig+1]
                af[mt][1] = As[(row + 8) * SPAD + k0 + tig];
                af[mt][2] = As[row * SPAD + k0 + tig + 4];      // A[row][2tig+8..]
                af[mt][3] = As[(row + 8) * SPAD + k0 + tig + 4];
            }
#pragma unroll
            for (int nt = 0; nt < 8; nt++) {
                int col = n_base + nt * 8 + gid;
                uint32_t b0 = Bs[col * SPAD + k0 + tig];        // B[2tig..][col]
                uint32_t b1 = Bs[col * SPAD + k0 + tig + 4];    // B[2tig+8..][col]
#pragma unroll
                for (int mt = 0; mt < 2; mt++) {
                    asm volatile(
                        "mma.sync.aligned.m16n8k16.row.col.f32.f16.f16.f32 "
                        "{%0,%1,%2,%3}, {%4,%5,%6,%7}, {%8,%9}, {%0,%1,%2,%3};"
                        : "+f"(acc[mt][nt][0]), "+f"(acc[mt][nt][1]),
                          "+f"(acc[mt][nt][2]), "+f"(acc[mt][nt][3])
                        : "r"(af[mt][0]), "r"(af[mt][1]), "r"(af[mt][2]), "r"(af[mt][3]),
                          "r"(b0), "r"(b1));
                }
            }
        }
    }

    // ---- epilogue ----
#pragma unroll
    for (int nt = 0; nt < 8; nt++) {
        int cg = bx * 128 + n_base + nt * 8 + 2 * tig;
        float bz0 = bias[cg], bz1 = bias[cg + 1];
#pragma unroll
        for (int mt = 0; mt < 2; mt++) {
            float v0 = acc[mt][nt][0] + bz0;
            float v1 = acc[mt][nt][1] + bz1;
            float v2 = acc[mt][nt][2] + bz0;
            float v3 = acc[mt][nt][3] + bz1;
            if (RELU) {
                v0 = fmaxf(v0, 0.f); v1 = fmaxf(v1, 0.f);
                v2 = fmaxf(v2, 0.f); v3 = fmaxf(v3, 0.f);
            }
            if (POOL) {
                float m0 = fmaxf(v0, v2);
                float m1 = fmaxf(v1, v3);
#pragma unroll
                for (int off = 4; off <= 16; off <<= 1) {
                    m0 = fmaxf(m0, __shfl_xor_sync(0xFFFFFFFFu, m0, off));
                    m1 = fmaxf(m1, __shfl_xor_sync(0xFFFFFFFFu, m1, off));
                }
                if (gid == 0) {
                    int q = (by * 128 + m_base + mt * 16) >> 4;
                    __half* C = (__half*)Cv;
                    *(__half2*)(C + (size_t)q * N + cg) = __floats2half2_rn(m0, m1);
                }
            } else if (HALF_OUT) {
                int rg = by * 128 + m_base + mt * 16 + gid;
                __half* C = (__half*)Cv;
                *(__half2*)(C + (size_t)rg * N + cg)       = __floats2half2_rn(v0, v1);
                *(__half2*)(C + (size_t)(rg + 8) * N + cg) = __floats2half2_rn(v2, v3);
            } else {
                int rg = by * 128 + m_base + mt * 16 + gid;
                float* C = (float*)Cv;
                *(float2*)(C + (size_t)rg * N + cg)       = make_float2(v0, v1);
                *(float2*)(C + (size_t)(rg + 8) * N + cg) = make_float2(v2, v3);
            }
        }
    }
}

// ---------------- mask fill --------------------------------------------------------
__global__ void fill_mask(float* m)
{
    int i = blockIdx.x * 256 + threadIdx.x;
    if (i < QQ) m[i] = 1.0f;
}

// ---------------- launcher ---------------------------------------------------------
extern "C" void kernel_launch(void* const* d_in, const int* in_sizes, int n_in,
                              void* d_out, int out_size)
{
    const float* coords = (const float*)d_in[0];
    const float* feats  = (const float*)d_in[1];
    const float* W1 = (const float*)d_in[2];  const float* b1 = (const float*)d_in[3];
    const float* W2 = (const float*)d_in[4];  const float* b2 = (const float*)d_in[5];
    const float* W3 = (const float*)d_in[6];  const float* b3 = (const float*)d_in[7];
    const float* W4 = (const float*)d_in[8];  const float* b4 = (const float*)d_in[9];
    const float* Wa1 = (const float*)d_in[10]; const float* ba1 = (const float*)d_in[11];
    const float* Wa2 = (const float*)d_in[12]; const float* ba2 = (const float*)d_in[13];

    float* out     = (float*)d_out;
    float* tokens  = out;                               // [QQ, DD]
    float* centout = out + (size_t)QQ * DD;             // [QQ, 4]
    float* masks   = centout + (size_t)QQ * 4;          // [QQ]

    __half *pA, *pB, *pPool, *pH, *pWt;
    int* pKnn;
    cudaGetSymbolAddress((void**)&pA, g_bufA);
    cudaGetSymbolAddress((void**)&pB, g_bufB);
    cudaGetSymbolAddress((void**)&pPool, g_pool);
    cudaGetSymbolAddress((void**)&pH, g_h);
    cudaGetSymbolAddress((void**)&pKnn, g_knn);
    cudaGetSymbolAddress((void**)&pWt, g_wt);

    // 1. FPS -> centroids
    fps_kernel<<<BB, 1024>>>(coords, centout);

    // 2. weight transposes (single kernel, fp16)
    transpose_all<<<(TE5 + 255) / 256, 256>>>(W2, W3, W4, Wa1, Wa2, pWt);

    // 3. kNN (64KB dynamic smem, tournament selection)
    cudaFuncSetAttribute(knn_kernel, cudaFuncAttributeMaxDynamicSharedMemorySize, PP * 8);
    knn_kernel<<<dim3(MM, BB), 256, PP * 8>>>(coords, pKnn);

    // 4. gather + layer1 (6 -> 256, relu, fp16 out) -> g_bufA
    gather_mlp1<<<RR / 8, 256>>>(feats, W1, b1);

    // 5. MLP chain on fp16 tensor cores; layer 4 fuses the max-pool
    cudaFuncSetAttribute((const void*)mma_gemm<true,  false, true >, cudaFuncAttributeMaxDynamicSharedMemorySize, GSMEM);
    cudaFuncSetAttribute((const void*)mma_gemm<false, true,  true >, cudaFuncAttributeMaxDynamicSharedMemorySize, GSMEM);
    cudaFuncSetAttribute((const void*)mma_gemm<false, false, false>, cudaFuncAttributeMaxDynamicSharedMemorySize, GSMEM);
    mma_gemm<true,  false, true ><<<dim3(512 / 128, RR / 128), 256, GSMEM>>>(pA, pWt + OFF_W2T, b2, pB, 512, 256);
    mma_gemm<true,  false, true ><<<dim3(768 / 128, RR / 128), 256, GSMEM>>>(pB, pWt + OFF_W3T, b3, pA, 768, 512);
    // layer 4: output pooled directly into g_pool [QQ, 768] (fp16)
    mma_gemm<false, true,  true ><<<dim3(768 / 128, RR / 128), 256, GSMEM>>>(pA, pWt + OFF_W4T, b4, pPool, 768, 768);

    // 6. attention MLP -> tokens (final layer fp32 out)
    mma_gemm<true,  false, true ><<<dim3(DD / 128, QQ / 128), 256, GSMEM>>>(pPool, pWt + OFF_WA1T, ba1, pH, 768, 768);
    mma_gemm<false, false, false><<<dim3(DD / 128, QQ / 128), 256, GSMEM>>>(pH, pWt + OFF_WA2T, ba2, tokens, 768, 768);

    // 7. masks
    fill_mask<<<(QQ + 255) / 256, 256>>>(masks);
}